// round 9
// baseline (speedup 1.0000x reference)
#include <cuda_runtime.h>
#include <math.h>

#define NB   8
#define C    256
#define H    112
#define W    112
#define L    224              // H + W
#define PLANES (NB * C)       // 2048
#define TOTAL4 (NB * C * H * W / 4)   // 6,422,528 float4

// scratch: pooled means [n][c][pos] (pos<112: W-mean per row h, else H-mean per col w)
__device__ __align__(16) float g_pool[NB * C * L];
__device__ __align__(16) float g_att [NB * C * L];

// ---------------------------------------------------------------------------
// Kernel 1: one block (224 thr, 7 warps) per (n,c) plane.
// Thread t loads float4 index t + 224*i (i<14): fully coalesced, all lanes
// active. Since 224 % 28 == 0, thread t owns fixed column-quad j=t%28 and
// rows g+8i (g=t/28): column sums accumulate in 4 registers; per-row partial
// (tree-sum of 4) goes to smem. Finale: pairwise trees, no shuffles anywhere.
// ---------------------------------------------------------------------------
__global__ void pool_kernel(const float* __restrict__ x) {
    const int plane = blockIdx.x;                 // n*C + c
    const float4* src = (const float4*)(x + (size_t)plane * (H * W));
    float* outp = g_pool + (size_t)plane * L;

    const int t = threadIdx.x;                    // 0..223
    const int g = t / 28;                         // row group 0..7
    const int j = t % 28;                         // column quad

    __shared__ float srow[112 * 29];              // [row][quad], pad 29
    __shared__ float scol[8][112];                // [group][column]

    float c0 = 0.f, c1 = 0.f, c2 = 0.f, c3 = 0.f;
    #pragma unroll
    for (int i = 0; i < 14; ++i) {
        float4 v = __ldg(&src[i * 224 + t]);      // row = g+8i, quad j
        srow[(g + 8 * i) * 29 + j] = (v.x + v.y) + (v.z + v.w);
        c0 += v.x; c1 += v.y; c2 += v.z; c3 += v.w;
    }
    scol[g][j * 4 + 0] = c0;
    scol[g][j * 4 + 1] = c1;
    scol[g][j * 4 + 2] = c2;
    scol[g][j * 4 + 3] = c3;
    __syncthreads();

    if (t < 112) {
        // row mean over W: pairwise tree over 28 partials
        const float* r = &srow[t * 29];
        float a[28];
        #pragma unroll
        for (int i = 0; i < 28; ++i) a[i] = r[i];
        float b[14];
        #pragma unroll
        for (int i = 0; i < 14; ++i) b[i] = a[2 * i] + a[2 * i + 1];
        float c[7];
        #pragma unroll
        for (int i = 0; i < 7; ++i) c[i] = b[2 * i] + b[2 * i + 1];
        float d0 = c[0] + c[1], d1 = c[2] + c[3], d2 = c[4] + c[5];
        float rsum = ((d0 + d1) + (d2 + c[6]));
        outp[t] = rsum * (1.f / (float)W);

        // column mean over H: pairwise tree over 8 group partials
        float e0 = scol[0][t] + scol[1][t];
        float e1 = scol[2][t] + scol[3][t];
        float e2 = scol[4][t] + scol[5][t];
        float e3 = scol[6][t] + scol[7][t];
        outp[112 + t] = ((e0 + e1) + (e2 + e3)) * (1.f / (float)H);
    }
}

// ---------------------------------------------------------------------------
// Kernel 2: per-(n,pos) block (1792 blocks, 256 threads): BN -> ds (C->8) ->
// ReLU -> us (8->C) -> sigmoid. Writes attention g_att[n][c][pos].
// ---------------------------------------------------------------------------
__global__ void att_kernel(const float* __restrict__ g1, const float* __restrict__ b1,
                           const float* __restrict__ m1, const float* __restrict__ v1,
                           const float* __restrict__ g2, const float* __restrict__ b2,
                           const float* __restrict__ m2, const float* __restrict__ v2,
                           const float* __restrict__ dsw, const float* __restrict__ dsb,
                           const float* __restrict__ usw, const float* __restrict__ usb) {
    const int b   = blockIdx.x;        // n*L + pos
    const int n   = b / L;
    const int pos = b % L;
    const int c   = threadIdx.x;       // 256

    float val = g_pool[((size_t)n * C + c) * L + pos];

    float sc, tb;
    if (pos < H) {
        float s = g1[c] * rsqrtf(v1[c] + 1e-5f);
        sc = s; tb = b1[c] - m1[c] * s;
    } else {
        float s = g2[c] * rsqrtf(v2[c] + 1e-5f);
        sc = s; tb = b2[c] - m2[c] * s;
    }
    val = fmaf(val, sc, tb);

    // down-projection partials: p[m] = dsw[m][c] * val
    float p[8];
    #pragma unroll
    for (int m = 0; m < 8; ++m) p[m] = dsw[m * C + c] * val;

    #pragma unroll
    for (int off = 16; off; off >>= 1) {
        #pragma unroll
        for (int m = 0; m < 8; ++m)
            p[m] += __shfl_down_sync(0xffffffffu, p[m], off);
    }

    __shared__ float wp[8][8];   // [warp][m]
    __shared__ float dv[8];
    const int warp = c >> 5, lane = c & 31;
    if (lane == 0) {
        #pragma unroll
        for (int m = 0; m < 8; ++m) wp[warp][m] = p[m];
    }
    __syncthreads();
    if (c < 8) {
        float s = dsb[c];
        #pragma unroll
        for (int w8 = 0; w8 < 8; ++w8) s += wp[w8][c];
        dv[c] = fmaxf(s, 0.f);       // ReLU
    }
    __syncthreads();

    float u = usb[c];
    #pragma unroll
    for (int m = 0; m < 8; ++m) u = fmaf(usw[c * 8 + m], dv[m], u);

    float a = 1.f / (1.f + expf(-u));  // sigmoid
    g_att[((size_t)n * C + c) * L + pos] = a;
}

// ---------------------------------------------------------------------------
// Kernel 3: out = hswish(x * a_w * a_h + x). Reversed block order (MRU-first
// vs pool's fill order), non-allocating stores, 8 float4/thread.
// ---------------------------------------------------------------------------
__device__ __forceinline__ float hsw(float v, float aw, float ah) {
    float t = fmaf(v * aw, ah, v);                       // v*aw*ah + v
    return t * __saturatef((t + 3.f) * (1.f / 6.f));     // t * clip(t+3,0,6)/6
}

__global__ void apply_kernel(const float4* __restrict__ x, float4* __restrict__ out) {
    const int rbid = gridDim.x - 1 - blockIdx.x;          // reverse traversal
    const int base = rbid * 2048 + threadIdx.x;
    #pragma unroll
    for (int k = 0; k < 8; ++k) {
        const int idx   = base + k * 256;
        const int w4    = idx % 28;
        const int rest  = idx / 28;
        const int h     = rest % H;
        const int plane = rest / H;                       // n*C + c

        const float  ah = __ldg(&g_att[(size_t)plane * L + h]);
        const float4 aw = __ldg((const float4*)&g_att[(size_t)plane * L + H + w4 * 4]);
        float4 v = __ldg(&x[idx]);

        float4 r;
        r.x = hsw(v.x, aw.x, ah);
        r.y = hsw(v.y, aw.y, ah);
        r.z = hsw(v.z, aw.z, ah);
        r.w = hsw(v.w, aw.w, ah);
        __stwt(&out[idx], r);     // write-through: don't allocate in L2
    }
}

// ---------------------------------------------------------------------------
extern "C" void kernel_launch(void* const* d_in, const int* in_sizes, int n_in,
                              void* d_out, int out_size) {
    const float* x   = (const float*)d_in[0];
    const float* g1  = (const float*)d_in[1];
    const float* b1  = (const float*)d_in[2];
    const float* m1  = (const float*)d_in[3];
    const float* v1  = (const float*)d_in[4];
    const float* g2  = (const float*)d_in[5];
    const float* b2  = (const float*)d_in[6];
    const float* m2  = (const float*)d_in[7];
    const float* v2  = (const float*)d_in[8];
    const float* dsw = (const float*)d_in[9];
    const float* dsb = (const float*)d_in[10];
    const float* usw = (const float*)d_in[11];
    const float* usb = (const float*)d_in[12];
    float* out = (float*)d_out;

    pool_kernel<<<PLANES, 224>>>(x);
    att_kernel<<<NB * L, C>>>(g1, b1, m1, v1, g2, b2, m2, v2, dsw, dsb, usw, usb);
    apply_kernel<<<TOTAL4 / 2048, 256>>>((const float4*)x, (float4*)out);
}

// round 12
// speedup vs baseline: 1.0396x; 1.0396x over previous
#include <cuda_runtime.h>
#include <math.h>

#define NB   8
#define C    256
#define H    112
#define W    112
#define L    224              // H + W
#define PLANES (NB * C)       // 2048
#define TOTAL8 (NB * C * H * W / 8)   // 3,211,264 float8 chunks

// scratch: pooled means [n][c][pos] (pos<112: W-mean per row h, else H-mean per col w)
__device__ __align__(16) float g_pool[NB * C * L];
__device__ __align__(16) float g_att [NB * C * L];

// 256-bit x load: non-coherent + L2 evict_last (pin x in L2 across kernels/replays)
__device__ __forceinline__ void ldg_el8(const float* p, float4& a, float4& b) {
    unsigned long long x0, x1, x2, x3;
    asm("ld.global.nc.L2::evict_last.v4.b64 {%0,%1,%2,%3}, [%4];"
        : "=l"(x0), "=l"(x1), "=l"(x2), "=l"(x3) : "l"(p));
    a.x = __uint_as_float((unsigned)x0); a.y = __uint_as_float((unsigned)(x0 >> 32));
    a.z = __uint_as_float((unsigned)x1); a.w = __uint_as_float((unsigned)(x1 >> 32));
    b.x = __uint_as_float((unsigned)x2); b.y = __uint_as_float((unsigned)(x2 >> 32));
    b.z = __uint_as_float((unsigned)x3); b.w = __uint_as_float((unsigned)(x3 >> 32));
}
// 256-bit out store: L2 evict_first (stream self-evicts instead of evicting x)
__device__ __forceinline__ void stg_ef8(float* p, float4 a, float4 b) {
    unsigned long long x0 = (unsigned long long)__float_as_uint(a.x) |
                            ((unsigned long long)__float_as_uint(a.y) << 32);
    unsigned long long x1 = (unsigned long long)__float_as_uint(a.z) |
                            ((unsigned long long)__float_as_uint(a.w) << 32);
    unsigned long long x2 = (unsigned long long)__float_as_uint(b.x) |
                            ((unsigned long long)__float_as_uint(b.y) << 32);
    unsigned long long x3 = (unsigned long long)__float_as_uint(b.z) |
                            ((unsigned long long)__float_as_uint(b.w) << 32);
    asm volatile("st.global.L2::evict_first.v4.b64 [%0], {%1,%2,%3,%4};"
                 :: "l"(p), "l"(x0), "l"(x1), "l"(x2), "l"(x3) : "memory");
}

// ---------------------------------------------------------------------------
// Kernel 1: one block (224 thr, 7 warps) per (n,c) plane, float8 accesses.
// Thread t loads float8 chunk t + 224*i (i<7): fully coalesced, all lanes
// active. 224 % 14 == 0 -> thread owns fixed column-octet j=t%14, rows g+16i
// (g=t/14, 0..15). 8 register column accumulators; per-row partials via smem;
// pairwise-tree finale.
// ---------------------------------------------------------------------------
__global__ void pool_kernel(const float* __restrict__ x) {
    const int plane = blockIdx.x;                 // n*C + c
    const float* src = x + (size_t)plane * (H * W);
    float* outp = g_pool + (size_t)plane * L;

    const int t = threadIdx.x;                    // 0..223
    const int g = t / 14;                         // row group 0..15
    const int j = t % 14;                         // column octet

    __shared__ float srow[112 * 15];              // [row][octet], pad 15
    __shared__ float scol[16][112];               // [group][column]

    float c0 = 0.f, c1 = 0.f, c2 = 0.f, c3 = 0.f;
    float c4 = 0.f, c5 = 0.f, c6 = 0.f, c7 = 0.f;
    #pragma unroll
    for (int i = 0; i < 7; ++i) {
        float4 a, b;
        ldg_el8(src + (i * 224 + t) * 8, a, b);   // row = g+16i, octet j
        srow[(g + 16 * i) * 15 + j] =
            ((a.x + a.y) + (a.z + a.w)) + ((b.x + b.y) + (b.z + b.w));
        c0 += a.x; c1 += a.y; c2 += a.z; c3 += a.w;
        c4 += b.x; c5 += b.y; c6 += b.z; c7 += b.w;
    }
    scol[g][j * 8 + 0] = c0;  scol[g][j * 8 + 1] = c1;
    scol[g][j * 8 + 2] = c2;  scol[g][j * 8 + 3] = c3;
    scol[g][j * 8 + 4] = c4;  scol[g][j * 8 + 5] = c5;
    scol[g][j * 8 + 6] = c6;  scol[g][j * 8 + 7] = c7;
    __syncthreads();

    if (t < 112) {
        // row mean over W: pairwise tree over 14 octet partials
        const float* r = &srow[t * 15];
        float a[14];
        #pragma unroll
        for (int i = 0; i < 14; ++i) a[i] = r[i];
        float b[7];
        #pragma unroll
        for (int i = 0; i < 7; ++i) b[i] = a[2 * i] + a[2 * i + 1];
        float d0 = b[0] + b[1], d1 = b[2] + b[3], d2 = b[4] + b[5];
        outp[t] = ((d0 + d1) + (d2 + b[6])) * (1.f / (float)W);

        // column mean over H: pairwise tree over 16 group partials
        float e[8];
        #pragma unroll
        for (int i = 0; i < 8; ++i) e[i] = scol[2 * i][t] + scol[2 * i + 1][t];
        float f0 = e[0] + e[1], f1 = e[2] + e[3];
        float f2 = e[4] + e[5], f3 = e[6] + e[7];
        outp[112 + t] = ((f0 + f1) + (f2 + f3)) * (1.f / (float)H);
    }
}

// ---------------------------------------------------------------------------
// Kernel 2: per-(n,pos) block (1792 blocks, 256 threads): BN -> ds (C->8) ->
// ReLU -> us (8->C) -> sigmoid. Writes attention g_att[n][c][pos].
// ---------------------------------------------------------------------------
__global__ void att_kernel(const float* __restrict__ g1, const float* __restrict__ b1,
                           const float* __restrict__ m1, const float* __restrict__ v1,
                           const float* __restrict__ g2, const float* __restrict__ b2,
                           const float* __restrict__ m2, const float* __restrict__ v2,
                           const float* __restrict__ dsw, const float* __restrict__ dsb,
                           const float* __restrict__ usw, const float* __restrict__ usb) {
    const int b   = blockIdx.x;        // n*L + pos
    const int n   = b / L;
    const int pos = b % L;
    const int c   = threadIdx.x;       // 256

    float val = g_pool[((size_t)n * C + c) * L + pos];

    float sc, tb;
    if (pos < H) {
        float s = g1[c] * rsqrtf(v1[c] + 1e-5f);
        sc = s; tb = b1[c] - m1[c] * s;
    } else {
        float s = g2[c] * rsqrtf(v2[c] + 1e-5f);
        sc = s; tb = b2[c] - m2[c] * s;
    }
    val = fmaf(val, sc, tb);

    // down-projection partials: p[m] = dsw[m][c] * val
    float p[8];
    #pragma unroll
    for (int m = 0; m < 8; ++m) p[m] = dsw[m * C + c] * val;

    #pragma unroll
    for (int off = 16; off; off >>= 1) {
        #pragma unroll
        for (int m = 0; m < 8; ++m)
            p[m] += __shfl_down_sync(0xffffffffu, p[m], off);
    }

    __shared__ float wp[8][8];   // [warp][m]
    __shared__ float dv[8];
    const int warp = c >> 5, lane = c & 31;
    if (lane == 0) {
        #pragma unroll
        for (int m = 0; m < 8; ++m) wp[warp][m] = p[m];
    }
    __syncthreads();
    if (c < 8) {
        float s = dsb[c];
        #pragma unroll
        for (int w8 = 0; w8 < 8; ++w8) s += wp[w8][c];
        dv[c] = fmaxf(s, 0.f);       // ReLU
    }
    __syncthreads();

    float u = usb[c];
    #pragma unroll
    for (int m = 0; m < 8; ++m) u = fmaf(usw[c * 8 + m], dv[m], u);

    float a = 1.f / (1.f + expf(-u));  // sigmoid
    g_att[((size_t)n * C + c) * L + pos] = a;
}

// ---------------------------------------------------------------------------
// Kernel 3: out = hswish(x * a_w * a_h + x). 2 float8/thread, block-contiguous
// 512 float8, reversed traversal + evict_last x reads, evict_first out stores.
// ---------------------------------------------------------------------------
__device__ __forceinline__ float hsw(float v, float aw, float ah) {
    float t = fmaf(v * aw, ah, v);                       // v*aw*ah + v
    return t * __saturatef((t + 3.f) * (1.f / 6.f));     // t * clip(t+3,0,6)/6
}

__global__ void apply_kernel(const float* __restrict__ x, float* __restrict__ out) {
    const int rbid = gridDim.x - 1 - blockIdx.x;          // reverse traversal
    const int base = rbid * 512 + threadIdx.x;
    #pragma unroll
    for (int k = 0; k < 2; ++k) {
        const int idx   = base + k * 256;                 // float8 index
        const int w8    = idx % 14;
        const int rest  = idx / 14;
        const int h     = rest % H;
        const int plane = rest / H;                       // n*C + c

        const float  ah  = __ldg(&g_att[(size_t)plane * L + h]);
        const float4 aw0 = __ldg((const float4*)&g_att[(size_t)plane * L + H + w8 * 8]);
        const float4 aw1 = __ldg((const float4*)&g_att[(size_t)plane * L + H + w8 * 8 + 4]);
        float4 va, vb;
        ldg_el8(x + (size_t)idx * 8, va, vb);

        float4 ra, rb;
        ra.x = hsw(va.x, aw0.x, ah);  ra.y = hsw(va.y, aw0.y, ah);
        ra.z = hsw(va.z, aw0.z, ah);  ra.w = hsw(va.w, aw0.w, ah);
        rb.x = hsw(vb.x, aw1.x, ah);  rb.y = hsw(vb.y, aw1.y, ah);
        rb.z = hsw(vb.z, aw1.z, ah);  rb.w = hsw(vb.w, aw1.w, ah);
        stg_ef8(out + (size_t)idx * 8, ra, rb);
    }
}

// ---------------------------------------------------------------------------
extern "C" void kernel_launch(void* const* d_in, const int* in_sizes, int n_in,
                              void* d_out, int out_size) {
    const float* x   = (const float*)d_in[0];
    const float* g1  = (const float*)d_in[1];
    const float* b1  = (const float*)d_in[2];
    const float* m1  = (const float*)d_in[3];
    const float* v1  = (const float*)d_in[4];
    const float* g2  = (const float*)d_in[5];
    const float* b2  = (const float*)d_in[6];
    const float* m2  = (const float*)d_in[7];
    const float* v2  = (const float*)d_in[8];
    const float* dsw = (const float*)d_in[9];
    const float* dsb = (const float*)d_in[10];
    const float* usw = (const float*)d_in[11];
    const float* usb = (const float*)d_in[12];
    float* out = (float*)d_out;

    pool_kernel<<<PLANES, 224>>>(x);
    att_kernel<<<NB * L, C>>>(g1, b1, m1, v1, g2, b2, m2, v2, dsw, dsb, usw, usb);
    apply_kernel<<<TOTAL8 / 512, 256>>>(x, out);
}